// round 2
// baseline (speedup 1.0000x reference)
#include <cuda_runtime.h>

#define N_SEG   65536
#define TOTAL   2097152
#define D       128
#define THREADS 256
#define WARPS_PER_BLOCK (THREADS / 32)

// 1 -> indptr is int32, 0 -> indptr is int64
__device__ int g_indptr_is32;

__global__ void detect_dtype_kernel(const int* __restrict__ indptr32) {
    // Safe probe: word 65536 exists in both layouts.
    // int32 layout: indptr32[65536] == TOTAL (last element).
    // int64 layout: indptr32[65536] == high word of indptr[32768] == 0.
    g_indptr_is32 = (indptr32[N_SEG] == TOTAL) ? 1 : 0;
}

__global__ __launch_bounds__(THREADS)
void segment_csr_kernel(const float* __restrict__ x,
                        const void* __restrict__ indptr_raw,
                        float* __restrict__ out) {
    const int warp = (blockIdx.x * WARPS_PER_BLOCK) + (threadIdx.x >> 5);
    const int lane = threadIdx.x & 31;
    if (warp >= N_SEG) return;

    long long s, e;
    if (g_indptr_is32) {
        const int* p = (const int*)indptr_raw;
        s = p[warp];
        e = p[warp + 1];
    } else {
        const long long* p = (const long long*)indptr_raw;
        s = p[warp];
        e = p[warp + 1];
    }

    // lane l owns columns [4l, 4l+4) as one float4 -> each row is a single
    // fully-coalesced 512B warp transaction.
    float4 a0 = make_float4(0.f, 0.f, 0.f, 0.f);
    float4 a1 = make_float4(0.f, 0.f, 0.f, 0.f);

    long long r = s;
    for (; r + 2 <= e; r += 2) {
        const float4 v0 = reinterpret_cast<const float4*>(x + r * D)[lane];
        const float4 v1 = reinterpret_cast<const float4*>(x + (r + 1) * D)[lane];
        a0.x += v0.x; a0.y += v0.y; a0.z += v0.z; a0.w += v0.w;
        a1.x += v1.x; a1.y += v1.y; a1.z += v1.z; a1.w += v1.w;
    }
    if (r < e) {
        const float4 v0 = reinterpret_cast<const float4*>(x + r * D)[lane];
        a0.x += v0.x; a0.y += v0.y; a0.z += v0.z; a0.w += v0.w;
    }

    a0.x += a1.x; a0.y += a1.y; a0.z += a1.z; a0.w += a1.w;

    reinterpret_cast<float4*>(out + (long long)warp * D)[lane] = a0;
}

extern "C" void kernel_launch(void* const* d_in, const int* in_sizes, int n_in,
                              void* d_out, int out_size) {
    const float* x    = (const float*)d_in[0];
    const void* indptr = d_in[1];
    float* out        = (float*)d_out;

    detect_dtype_kernel<<<1, 1>>>((const int*)indptr);

    const int blocks = (N_SEG + WARPS_PER_BLOCK - 1) / WARPS_PER_BLOCK;
    segment_csr_kernel<<<blocks, THREADS>>>(x, indptr, out);
}

// round 3
// speedup vs baseline: 1.2048x; 1.2048x over previous
#include <cuda_runtime.h>

#define N_SEG   65536
#define TOTAL   2097152
#define D       128
#define THREADS 64
#define WARPS_PER_BLOCK (THREADS / 32)

// 1 -> indptr is int32, 0 -> indptr is int64
__device__ int g_indptr_is32;

__global__ void detect_dtype_kernel(const int* __restrict__ indptr32) {
    // Safe probe: word 65536 exists in both layouts.
    // int32 layout: indptr32[65536] == TOTAL (last element).
    // int64 layout: indptr32[65536] == high word of indptr[32768] == 0.
    g_indptr_is32 = (indptr32[N_SEG] == TOTAL) ? 1 : 0;
}

__device__ __forceinline__ void acc4(float4& a, const float4 v) {
    a.x += v.x; a.y += v.y; a.z += v.z; a.w += v.w;
}

__global__ __launch_bounds__(THREADS)
void segment_csr_kernel(const float* __restrict__ x,
                        const void* __restrict__ indptr_raw,
                        float* __restrict__ out) {
    const int warp = (blockIdx.x * WARPS_PER_BLOCK) + (threadIdx.x >> 5);
    const int lane = threadIdx.x & 31;
    if (warp >= N_SEG) return;

    long long s, e;
    if (g_indptr_is32) {
        const int* p = (const int*)indptr_raw;
        s = p[warp];
        e = p[warp + 1];
    } else {
        const long long* p = (const long long*)indptr_raw;
        s = p[warp];
        e = p[warp + 1];
    }

    // lane l owns columns [4l, 4l+4): each row is one fully-coalesced 512B
    // warp transaction. 4-way unroll -> 4 independent LDG.128 in flight.
    const float4* xr = reinterpret_cast<const float4*>(x) + lane;

    float4 a0 = make_float4(0.f, 0.f, 0.f, 0.f);
    float4 a1 = make_float4(0.f, 0.f, 0.f, 0.f);
    float4 a2 = make_float4(0.f, 0.f, 0.f, 0.f);
    float4 a3 = make_float4(0.f, 0.f, 0.f, 0.f);

    long long r = s;
    for (; r + 4 <= e; r += 4) {
        const float4 v0 = __ldcs(xr + (r    ) * 32);
        const float4 v1 = __ldcs(xr + (r + 1) * 32);
        const float4 v2 = __ldcs(xr + (r + 2) * 32);
        const float4 v3 = __ldcs(xr + (r + 3) * 32);
        acc4(a0, v0); acc4(a1, v1); acc4(a2, v2); acc4(a3, v3);
    }
    for (; r < e; ++r) {
        acc4(a0, __ldcs(xr + r * 32));
    }

    acc4(a0, a1); acc4(a2, a3); acc4(a0, a2);

    __stcs(reinterpret_cast<float4*>(out) + (long long)warp * 32 + lane, a0);
}

extern "C" void kernel_launch(void* const* d_in, const int* in_sizes, int n_in,
                              void* d_out, int out_size) {
    const float* x     = (const float*)d_in[0];
    const void* indptr = d_in[1];
    float* out         = (float*)d_out;

    detect_dtype_kernel<<<1, 1>>>((const int*)indptr);

    const int blocks = (N_SEG + WARPS_PER_BLOCK - 1) / WARPS_PER_BLOCK;
    segment_csr_kernel<<<blocks, THREADS>>>(x, indptr, out);
}